// round 1
// baseline (speedup 1.0000x reference)
#include <cuda_runtime.h>
#include <math_constants.h>
#include <cstdint>

#define BMAX 2
#define NMAX 8192
#define KNN 3
#define TILE 2048
#define THREADS 256
#define WARPS 8
#define WQ 4
#define QPB (WARPS * WQ)   // 32 queries per block

// Scratch: precomputed targets p = xyz1 + flow1, with w = |p|^2.  256 KB, L2-resident.
__device__ float4 g_targets[BMAX * NMAX];

__global__ void prep_kernel(const float* __restrict__ xyz1,
                            const float* __restrict__ flow1,
                            int B, int N) {
    int idx = blockIdx.x * blockDim.x + threadIdx.x;
    if (idx >= B * N) return;
    int b = idx / N;
    int i = idx - b * N;
    const float* x = xyz1 + (size_t)b * 3 * N;
    const float* f = flow1 + (size_t)b * 3 * N;
    float px = x[i]         + f[i];
    float py = x[N + i]     + f[N + i];
    float pz = x[2 * N + i] + f[2 * N + i];
    float s = fmaf(px, px, fmaf(py, py, pz * pz));
    g_targets[b * N + i] = make_float4(px, py, pz, s);
}

__global__ void __launch_bounds__(THREADS)
knn_warp_kernel(const float* __restrict__ xyz2,
                const float* __restrict__ flow1,
                float* __restrict__ out,
                int N) {
    __shared__ float4 sh[TILE];

    const int tid  = threadIdx.x;
    const int warp = tid >> 5;
    const int lane = tid & 31;

    const int qglobal = blockIdx.x * QPB;     // first query of this block (global over B*N)
    const int b       = qglobal / N;          // whole block in one batch (N % QPB == 0)
    const int n2base  = (qglobal - b * N) + warp * WQ;

    const float* X2 = xyz2 + (size_t)b * 3 * N;

    // Per-query scaled coords for the 3-FMA score:  s = p.w + p.x*(-2qx) + p.y*(-2qy) + p.z*(-2qz)
    float m2x[WQ], m2y[WQ], m2z[WQ];
#pragma unroll
    for (int q = 0; q < WQ; q++) {
        int n2 = n2base + q;
        m2x[q] = -2.0f * X2[n2];
        m2y[q] = -2.0f * X2[N + n2];
        m2z[q] = -2.0f * X2[2 * N + n2];
    }

    float bs[WQ][KNN];
    int   bi[WQ][KNN];
#pragma unroll
    for (int q = 0; q < WQ; q++)
#pragma unroll
        for (int k = 0; k < KNN; k++) { bs[q][k] = CUDART_INF_F; bi[q][k] = 0x7fffffff; }

    const float4* tgt = g_targets + (size_t)b * N;

    for (int t0 = 0; t0 < N; t0 += TILE) {
        __syncthreads();
#pragma unroll
        for (int i = tid; i < TILE; i += THREADS)
            sh[i] = tgt[t0 + i];
        __syncthreads();

#pragma unroll 4
        for (int j = 0; j < TILE / 32; j++) {
            const int c = j * 32 + lane;           // conflict-free (consecutive float4 per lane)
            const float4 p = sh[c];
            const int gidx = t0 + c;
#pragma unroll
            for (int q = 0; q < WQ; q++) {
                float s = fmaf(p.x, m2x[q], fmaf(p.y, m2y[q], fmaf(p.z, m2z[q], p.w)));
                if (s < bs[q][2]) {                 // rare path: top-3 insert
                    if (s < bs[q][1]) {
                        bs[q][2] = bs[q][1]; bi[q][2] = bi[q][1];
                        if (s < bs[q][0]) {
                            bs[q][1] = bs[q][0]; bi[q][1] = bi[q][0];
                            bs[q][0] = s;        bi[q][0] = gidx;
                        } else {
                            bs[q][1] = s;        bi[q][1] = gidx;
                        }
                    } else {
                        bs[q][2] = s;            bi[q][2] = gidx;
                    }
                }
            }
        }
    }

    // Butterfly merge of per-lane top-3s.  Snapshot originals before exchange so both
    // partners merge un-mutated triples (avoids duplicate insertion).
#pragma unroll
    for (int off = 16; off > 0; off >>= 1) {
#pragma unroll
        for (int q = 0; q < WQ; q++) {
            float o0 = bs[q][0], o1 = bs[q][1], o2 = bs[q][2];
            int   j0 = bi[q][0], j1 = bi[q][1], j2 = bi[q][2];
            float rs0 = __shfl_xor_sync(0xffffffffu, o0, off);
            int   ri0 = __shfl_xor_sync(0xffffffffu, j0, off);
            float rs1 = __shfl_xor_sync(0xffffffffu, o1, off);
            int   ri1 = __shfl_xor_sync(0xffffffffu, j1, off);
            float rs2 = __shfl_xor_sync(0xffffffffu, o2, off);
            int   ri2 = __shfl_xor_sync(0xffffffffu, j2, off);

            float cs[3] = {rs0, rs1, rs2};
            int   ci[3] = {ri0, ri1, ri2};
#pragma unroll
            for (int k = 0; k < 3; k++) {
                float s = cs[k]; int id = ci[k];
                // lexicographic (score, index): matches top_k lower-index tie-break
                if (s < bs[q][2] || (s == bs[q][2] && id < bi[q][2])) {
                    if (s < bs[q][1] || (s == bs[q][1] && id < bi[q][1])) {
                        bs[q][2] = bs[q][1]; bi[q][2] = bi[q][1];
                        if (s < bs[q][0] || (s == bs[q][0] && id < bi[q][0])) {
                            bs[q][1] = bs[q][0]; bi[q][1] = bi[q][0];
                            bs[q][0] = s;        bi[q][0] = id;
                        } else {
                            bs[q][1] = s;        bi[q][1] = id;
                        }
                    } else {
                        bs[q][2] = s;            bi[q][2] = id;
                    }
                }
            }
        }
    }

    // Lanes 0..WQ-1 finalize one query each (all lanes hold the merged result).
    if (lane < WQ) {
        const int q  = lane;
        const int n2 = n2base + q;
        const float qx = X2[n2];
        const float qy = X2[N + n2];
        const float qz = X2[2 * N + n2];

        float w[KNN];
        float wsum = 0.0f;
#pragma unroll
        for (int k = 0; k < KNN; k++) {
            float4 p = tgt[bi[q][k]];
            float dx = p.x - qx, dy = p.y - qy, dz = p.z - qz;
            float d = sqrtf(fmaf(dx, dx, fmaf(dy, dy, dz * dz)));
            d = fmaxf(d, 1e-10f);
            float inv = 1.0f / d;
            w[k] = inv;
            wsum += inv;
        }
        const float rs = 1.0f / wsum;

        const float* F = flow1 + (size_t)b * 3 * N;
        float fx = 0.0f, fy = 0.0f, fz = 0.0f;
#pragma unroll
        for (int k = 0; k < KNN; k++) {
            int id = bi[q][k];
            float ww = w[k] * rs;
            fx = fmaf(ww, F[id],         fx);
            fy = fmaf(ww, F[N + id],     fy);
            fz = fmaf(ww, F[2 * N + id], fz);
        }

        float* O = out + (size_t)b * 3 * N;
        O[n2]         = qx - fx;
        O[N + n2]     = qy - fy;
        O[2 * N + n2] = qz - fz;
    }
}

extern "C" void kernel_launch(void* const* d_in, const int* in_sizes, int n_in,
                              void* d_out, int out_size) {
    const float* xyz1  = (const float*)d_in[0];
    const float* xyz2  = (const float*)d_in[1];
    const float* flow1 = (const float*)d_in[2];
    float* out = (float*)d_out;

    const int B = 2;
    const int N = in_sizes[0] / (3 * B);   // 8192

    int total = B * N;
    prep_kernel<<<(total + THREADS - 1) / THREADS, THREADS>>>(xyz1, flow1, B, N);

    int nblocks = total / QPB;             // 512
    knn_warp_kernel<<<nblocks, THREADS>>>(xyz2, flow1, out, N);
}